// round 1
// baseline (speedup 1.0000x reference)
#include <cuda_runtime.h>
#include <cstdint>

// Problem constants: B=16, N1=1024, N2=4096, DIM=512
// M1 = B*N1 = 16384 (K=1024), M2 = B*N2 = 65536 (K=512), N = 512

__device__ float g_h1[16384 * 512];        // fc1 output -> feats1 (in-place BN)
__device__ float g_h2[65536 * 512];        // fc2 output -> feats2 (in-place BN)
__device__ float g_part[2 * 128 * 512];    // per-block partial sums / sumsq
__device__ float g_ss[4 * 512];            // scale1, shift1, scale2, shift2

// ---------------------------------------------------------------------------
// GEMM: C[M,512] = A[M,K] @ W[K,512] + bias   (BM=128, BN=64, BK=16, 256 thr)
// ---------------------------------------------------------------------------
template <int K>
__global__ void __launch_bounds__(256) gemm_bias(
    const float* __restrict__ A, const float* __restrict__ W,
    const float* __restrict__ bias, float* __restrict__ C) {
  const int BM = 128, BN = 64, BK = 16;
  __shared__ float As[BK][BM + 4];
  __shared__ float Ws[BK][BN];

  const int bm = blockIdx.y * BM;
  const int bn = blockIdx.x * BN;
  const int tid = threadIdx.x;
  const int tr = tid >> 4;   // 0..15 -> 8-row group
  const int tc = tid & 15;   // 0..15 -> 4-col group

  float acc[8][4];
#pragma unroll
  for (int i = 0; i < 8; i++)
#pragma unroll
    for (int j = 0; j < 4; j++) acc[i][j] = 0.0f;

  for (int k0 = 0; k0 < K; k0 += BK) {
    // Load A tile 128x16 (float4 along K), store transposed
#pragma unroll
    for (int i = 0; i < 2; i++) {
      int s = tid + (i << 8);
      int m = s >> 2;
      int k4 = (s & 3) << 2;
      const float4 v = *reinterpret_cast<const float4*>(
          A + (size_t)(bm + m) * K + k0 + k4);
      As[k4 + 0][m] = v.x;
      As[k4 + 1][m] = v.y;
      As[k4 + 2][m] = v.z;
      As[k4 + 3][m] = v.w;
    }
    // Load W tile 16x64
    {
      int k = tid >> 4;
      int n4 = (tid & 15) << 2;
      *reinterpret_cast<float4*>(&Ws[k][n4]) =
          *reinterpret_cast<const float4*>(W + (size_t)(k0 + k) * 512 + bn + n4);
    }
    __syncthreads();

#pragma unroll
    for (int k = 0; k < BK; k++) {
      float4 a0 = *reinterpret_cast<const float4*>(&As[k][tr * 8]);
      float4 a1 = *reinterpret_cast<const float4*>(&As[k][tr * 8 + 4]);
      float4 wv = *reinterpret_cast<const float4*>(&Ws[k][tc * 4]);
      float av[8] = {a0.x, a0.y, a0.z, a0.w, a1.x, a1.y, a1.z, a1.w};
      float wr[4] = {wv.x, wv.y, wv.z, wv.w};
#pragma unroll
      for (int i = 0; i < 8; i++)
#pragma unroll
        for (int j = 0; j < 4; j++) acc[i][j] = fmaf(av[i], wr[j], acc[i][j]);
    }
    __syncthreads();
  }

  const int nbase = bn + tc * 4;
  float4 bvec = *reinterpret_cast<const float4*>(bias + nbase);
#pragma unroll
  for (int i = 0; i < 8; i++) {
    size_t m = (size_t)(bm + tr * 8 + i);
    float4 r;
    r.x = acc[i][0] + bvec.x;
    r.y = acc[i][1] + bvec.y;
    r.z = acc[i][2] + bvec.z;
    r.w = acc[i][3] + bvec.w;
    *reinterpret_cast<float4*>(C + m * 512 + nbase) = r;
  }
}

// ---------------------------------------------------------------------------
// Deterministic per-channel sum/sumsq: 128 blocks x 512 threads (thread=channel)
// ---------------------------------------------------------------------------
__global__ void __launch_bounds__(512) colreduce(const float* __restrict__ X,
                                                 int M, float* __restrict__ part) {
  int c = threadIdx.x;
  float s = 0.0f, sq = 0.0f;
  for (int r = blockIdx.x; r < M; r += 128) {
    float v = X[(size_t)r * 512 + c];
    s += v;
    sq += v * v;
  }
  part[blockIdx.x * 512 + c] = s;
  part[65536 + blockIdx.x * 512 + c] = sq;
}

// Combine 128 partials -> per-channel scale/shift (BN affine folded)
__global__ void __launch_bounds__(512) stats_finalize(
    const float* __restrict__ part, float invM,
    const float* __restrict__ gamma, const float* __restrict__ beta,
    float* __restrict__ ss) {
  int c = threadIdx.x;
  float s = 0.0f, sq = 0.0f;
  for (int b = 0; b < 128; b++) {
    s += part[b * 512 + c];
    sq += part[65536 + b * 512 + c];
  }
  float mu = s * invM;
  float var = sq * invM - mu * mu;
  float sc = gamma[c] * rsqrtf(var + 1e-5f);
  ss[c] = sc;
  ss[512 + c] = beta[c] - mu * sc;
}

// In-place y = relu(x*scale + shift), vectorized float4
__global__ void __launch_bounds__(256) bn_relu(float* __restrict__ X,
                                               size_t nVec4,
                                               const float* __restrict__ ss) {
  __shared__ float sc[512], sh[512];
  for (int c = threadIdx.x; c < 512; c += blockDim.x) {
    sc[c] = ss[c];
    sh[c] = ss[512 + c];
  }
  __syncthreads();
  float4* X4 = reinterpret_cast<float4*>(X);
  for (size_t i = blockIdx.x * (size_t)blockDim.x + threadIdx.x; i < nVec4;
       i += (size_t)gridDim.x * blockDim.x) {
    float4 v = X4[i];
    int c = (int)((i * 4) & 511);
    v.x = fmaxf(fmaf(v.x, sc[c + 0], sh[c + 0]), 0.0f);
    v.y = fmaxf(fmaf(v.y, sc[c + 1], sh[c + 1]), 0.0f);
    v.z = fmaxf(fmaf(v.z, sc[c + 2], sh[c + 2]), 0.0f);
    v.w = fmaxf(fmaf(v.w, sc[c + 3], sh[c + 3]), 0.0f);
    X4[i] = v;
  }
}

// ---------------------------------------------------------------------------
// 3-NN inverse-distance interpolation + add feats2. One block per dst point.
// ---------------------------------------------------------------------------
__global__ void __launch_bounds__(128) interp_add(
    const float* __restrict__ xyz2, const float* __restrict__ xyz1,
    const float* __restrict__ feats1, const float* __restrict__ feats2,
    float* __restrict__ outF) {
  __shared__ float sd[1024];
  __shared__ float rv[128];
  __shared__ int ri[128];
  __shared__ float b3v[3];
  __shared__ int b3i[3];

  const int tid = threadIdx.x;
  const int b = blockIdx.x >> 12;    // / 4096
  const int n = blockIdx.x & 4095;

  const float* pd = xyz2 + ((size_t)(b * 4096 + n)) * 3;
  const float px = pd[0], py = pd[1], pz = pd[2];
  const float pp = px * px + py * py + pz * pz;
  const float* src = xyz1 + (size_t)b * 1024 * 3;

  // Squared distances via the reference's expansion formula (no clamp)
  for (int s = tid; s < 1024; s += 128) {
    float sx = src[3 * s + 0];
    float sy = src[3 * s + 1];
    float sz = src[3 * s + 2];
    float ssn = sx * sx + sy * sy + sz * sz;
    float dt = px * sx + py * sy + pz * sz;
    sd[s] = pp + ssn - 2.0f * dt;
  }
  __syncthreads();

  // 3 rounds of block-wide argmin (tie-break: lowest index, matching top_k)
#pragma unroll
  for (int round = 0; round < 3; round++) {
    float lv = 1e30f;
    int li = 0x7fffffff;
#pragma unroll
    for (int j = 0; j < 8; j++) {
      int s = tid + j * 128;
      float v = sd[s];
      if (v < lv || (v == lv && s < li)) {
        lv = v;
        li = s;
      }
    }
    rv[tid] = lv;
    ri[tid] = li;
    __syncthreads();
    for (int off = 64; off > 0; off >>= 1) {
      if (tid < off) {
        float v2 = rv[tid + off];
        int i2 = ri[tid + off];
        if (v2 < rv[tid] || (v2 == rv[tid] && i2 < ri[tid])) {
          rv[tid] = v2;
          ri[tid] = i2;
        }
      }
      __syncthreads();
    }
    if (tid == 0) {
      b3v[round] = rv[0];
      b3i[round] = ri[0];
      sd[ri[0]] = 1e30f;
    }
    __syncthreads();
  }

  float w0 = 1.0f / (b3v[0] + 1e-8f);
  float w1 = 1.0f / (b3v[1] + 1e-8f);
  float w2 = 1.0f / (b3v[2] + 1e-8f);
  float inv = 1.0f / (w0 + w1 + w2);
  w0 *= inv;
  w1 *= inv;
  w2 *= inv;

  const float4* f0 =
      reinterpret_cast<const float4*>(feats1 + ((size_t)b * 1024 + b3i[0]) * 512);
  const float4* f1 =
      reinterpret_cast<const float4*>(feats1 + ((size_t)b * 1024 + b3i[1]) * 512);
  const float4* f2 =
      reinterpret_cast<const float4*>(feats1 + ((size_t)b * 1024 + b3i[2]) * 512);
  const float4* g =
      reinterpret_cast<const float4*>(feats2 + ((size_t)(b * 4096 + n)) * 512);
  float4* o = reinterpret_cast<float4*>(outF + ((size_t)(b * 4096 + n)) * 512);

  // 128 threads x 1 float4 = 512 channels
  float4 a0 = f0[tid], a1 = f1[tid], a2 = f2[tid], gg = g[tid];
  float4 r;
  r.x = w0 * a0.x + w1 * a1.x + w2 * a2.x + gg.x;
  r.y = w0 * a0.y + w1 * a1.y + w2 * a2.y + gg.y;
  r.z = w0 * a0.z + w1 * a1.z + w2 * a2.z + gg.z;
  r.w = w0 * a0.w + w1 * a1.w + w2 * a2.w + gg.w;
  o[tid] = r;
}

// ---------------------------------------------------------------------------
extern "C" void kernel_launch(void* const* d_in, const int* in_sizes, int n_in,
                              void* d_out, int out_size) {
  const float* xyz1 = (const float*)d_in[0];     // [16,1024,3]
  const float* points1 = (const float*)d_in[1];  // [16,1024,1024]
  const float* xyz2 = (const float*)d_in[2];     // [16,4096,3]
  const float* points2 = (const float*)d_in[3];  // [16,4096,512]
  const float* fc1_w = (const float*)d_in[4];    // [1024,512]
  const float* fc1_b = (const float*)d_in[5];
  const float* bn1_g = (const float*)d_in[6];
  const float* bn1_b = (const float*)d_in[7];
  const float* fc2_w = (const float*)d_in[8];    // [512,512]
  const float* fc2_b = (const float*)d_in[9];
  const float* bn2_g = (const float*)d_in[10];
  const float* bn2_b = (const float*)d_in[11];
  float* out = (float*)d_out;

  float *h1, *h2, *part, *ss;
  cudaGetSymbolAddress((void**)&h1, g_h1);
  cudaGetSymbolAddress((void**)&h2, g_h2);
  cudaGetSymbolAddress((void**)&part, g_part);
  cudaGetSymbolAddress((void**)&ss, g_ss);

  const size_t featElems = (size_t)16 * 4096 * 512;   // 33554432
  const size_t totalOut = (size_t)out_size;
  const size_t xyzElems = totalOut > featElems ? totalOut - featElems : 0;

  // Path 1: fc1 -> BN1 -> ReLU  (feats1 in g_h1)
  gemm_bias<1024><<<dim3(8, 128), 256>>>(points1, fc1_w, fc1_b, h1);
  colreduce<<<128, 512>>>(h1, 16384, part);
  stats_finalize<<<1, 512>>>(part, 1.0f / 16384.0f, bn1_g, bn1_b, ss);
  bn_relu<<<1024, 256>>>(h1, (size_t)16384 * 512 / 4, ss);

  // Path 2: fc2 -> BN2 -> ReLU  (feats2 in g_h2)
  gemm_bias<512><<<dim3(8, 512), 256>>>(points2, fc2_w, fc2_b, h2);
  colreduce<<<128, 512>>>(h2, 65536, part);
  stats_finalize<<<1, 512>>>(part, 1.0f / 65536.0f, bn2_g, bn2_b, ss + 1024);
  bn_relu<<<4096, 256>>>(h2, (size_t)65536 * 512 / 4, ss + 1024);

  // Output: [xyz2 passthrough | interp(feats1) + feats2]
  if (xyzElems > 0) {
    cudaMemcpyAsync(out, xyz2, xyzElems * sizeof(float),
                    cudaMemcpyDeviceToDevice);
  }
  interp_add<<<65536, 128>>>(xyz2, xyz1, h1, h2, out + xyzElems);
}

// round 3
// speedup vs baseline: 1.7187x; 1.7187x over previous
#include <cuda_runtime.h>
#include <cuda_bf16.h>
#include <cstdint>

// Problem constants: B=16, N1=1024, N2=4096, DIM=512
// GEMM1: M=16384, K=1024, N=512.  GEMM2: M=65536, K=512, N=512.

// ---------------- scratch (no allocations allowed) -------------------------
__device__ float g_h1[16384 * 512];
__device__ float g_h2[65536 * 512];
__device__ float g_part[2 * 128 * 512];
__device__ float g_ss[4 * 512];
__device__ __nv_bfloat16 g_a1h[16384 * 1024];
__device__ __nv_bfloat16 g_a1l[16384 * 1024];
__device__ __nv_bfloat16 g_a2h[65536 * 512];
__device__ __nv_bfloat16 g_a2l[65536 * 512];
__device__ __nv_bfloat16 g_w1h[512 * 1024];
__device__ __nv_bfloat16 g_w1l[512 * 1024];
__device__ __nv_bfloat16 g_w2h[512 * 512];
__device__ __nv_bfloat16 g_w2l[512 * 512];

// ---------------- low-level helpers ----------------------------------------
__device__ __forceinline__ uint32_t smem_to_u32(const void* p) {
  uint32_t a;
  asm("{ .reg .u64 t; cvta.to.shared.u64 t, %1; cvt.u32.u64 %0, t; }"
      : "=r"(a) : "l"(p));
  return a;
}
__device__ __forceinline__ void cp_async16(uint32_t dst, const void* src) {
  asm volatile("cp.async.cg.shared.global [%0], [%1], 16;" ::"r"(dst),
               "l"(src));
}
#define CP_COMMIT() asm volatile("cp.async.commit_group;" ::: "memory")
#define CP_WAIT(N) asm volatile("cp.async.wait_group %0;" ::"n"(N) : "memory")

__device__ __forceinline__ void ldsm_x4(uint32_t (&r)[4], uint32_t addr) {
  asm volatile(
      "ldmatrix.sync.aligned.m8n8.x4.shared.b16 {%0,%1,%2,%3}, [%4];"
      : "=r"(r[0]), "=r"(r[1]), "=r"(r[2]), "=r"(r[3])
      : "r"(addr));
}
__device__ __forceinline__ void mma_bf16(float (&c)[4], const uint32_t (&a)[4],
                                         uint32_t b0, uint32_t b1) {
  asm volatile(
      "mma.sync.aligned.m16n8k16.row.col.f32.bf16.bf16.f32 "
      "{%0,%1,%2,%3}, {%4,%5,%6,%7}, {%8,%9}, {%0,%1,%2,%3};"
      : "+f"(c[0]), "+f"(c[1]), "+f"(c[2]), "+f"(c[3])
      : "r"(a[0]), "r"(a[1]), "r"(a[2]), "r"(a[3]), "r"(b0), "r"(b1));
}

// ---------------------------------------------------------------------------
// fp32 -> (hi, lo) bf16 split (elementwise, vectorized)
// ---------------------------------------------------------------------------
__global__ void __launch_bounds__(256) fsplit(const float* __restrict__ X,
                                              __nv_bfloat16* __restrict__ hi,
                                              __nv_bfloat16* __restrict__ lo,
                                              size_t n4) {
  __nv_bfloat162* H = reinterpret_cast<__nv_bfloat162*>(hi);
  __nv_bfloat162* L = reinterpret_cast<__nv_bfloat162*>(lo);
  const float4* X4 = reinterpret_cast<const float4*>(X);
  for (size_t i = blockIdx.x * (size_t)blockDim.x + threadIdx.x; i < n4;
       i += (size_t)gridDim.x * blockDim.x) {
    float4 v = X4[i];
    __nv_bfloat16 h0 = __float2bfloat16(v.x);
    __nv_bfloat16 h1 = __float2bfloat16(v.y);
    __nv_bfloat16 h2 = __float2bfloat16(v.z);
    __nv_bfloat16 h3 = __float2bfloat16(v.w);
    __nv_bfloat16 l0 = __float2bfloat16(v.x - __bfloat162float(h0));
    __nv_bfloat16 l1 = __float2bfloat16(v.y - __bfloat162float(h1));
    __nv_bfloat16 l2 = __float2bfloat16(v.z - __bfloat162float(h2));
    __nv_bfloat16 l3 = __float2bfloat16(v.w - __bfloat162float(h3));
    H[2 * i] = __nv_bfloat162{h0, h1};
    H[2 * i + 1] = __nv_bfloat162{h2, h3};
    L[2 * i] = __nv_bfloat162{l0, l1};
    L[2 * i + 1] = __nv_bfloat162{l2, l3};
  }
}

// W [K,512] -> Wt hi/lo [512,K] transpose + split
__global__ void __launch_bounds__(256) wsplit(const float* __restrict__ W,
                                              __nv_bfloat16* __restrict__ Th,
                                              __nv_bfloat16* __restrict__ Tl,
                                              int K) {
  __shared__ float tl[32][33];
  int k0 = blockIdx.x * 32, n0 = blockIdx.y * 32;
  int x = threadIdx.x & 31, y = threadIdx.x >> 5;  // 32x8
  for (int i = y; i < 32; i += 8)
    tl[i][x] = W[(size_t)(k0 + i) * 512 + n0 + x];
  __syncthreads();
  for (int i = y; i < 32; i += 8) {
    float v = tl[x][i];  // = W[k0+x][n0+i]
    __nv_bfloat16 h = __float2bfloat16(v);
    __nv_bfloat16 l = __float2bfloat16(v - __bfloat162float(h));
    Th[(size_t)(n0 + i) * K + k0 + x] = h;
    Tl[(size_t)(n0 + i) * K + k0 + x] = l;
  }
}

// ---------------------------------------------------------------------------
// bf16x3 GEMM via mma.sync: C[M,512] = A[M,K] @ Wt[512,K]^T + bias
// CTA tile 128x128, Kc=64, cp.async double buffer, 256 thr, warp grid 2m x 4n.
// SMEM tiles padded: 64+8 bf16 per row (144B stride) -> conflict-free ldmatrix.
// ---------------------------------------------------------------------------
static constexpr int G_RS = 144;                 // smem row stride bytes
static constexpr int G_TILE = 128 * G_RS;        // 18432 B per matrix tile
static constexpr int G_STAGE = 4 * G_TILE;       // Ah, Al, Bh, Bl
static constexpr int GEMM_SMEM = 2 * G_STAGE;    // 147456 B

template <int K>
__device__ __forceinline__ void stage_load(
    const __nv_bfloat16* __restrict__ Ah, const __nv_bfloat16* __restrict__ Al,
    const __nv_bfloat16* __restrict__ Bh, const __nv_bfloat16* __restrict__ Bl,
    int bm, int bn, int k0, uint32_t base, int tid) {
  const __nv_bfloat16* srcs[4] = {Ah + (size_t)bm * K, Al + (size_t)bm * K,
                                  Bh + (size_t)bn * K, Bl + (size_t)bn * K};
#pragma unroll
  for (int t = 0; t < 4; t++) {
    const __nv_bfloat16* s = srcs[t];
    uint32_t tb = base + t * G_TILE;
#pragma unroll
    for (int i = 0; i < 4; i++) {
      int q = tid + i * 256;       // 0..1023
      int row = q >> 3, seg = q & 7;
      cp_async16(tb + row * G_RS + seg * 16,
                 s + (size_t)row * K + k0 + seg * 8);
    }
  }
}

__device__ __forceinline__ void stage_compute(uint32_t base, int warp_m,
                                              int warp_n, int lid,
                                              float acc[4][4][4]) {
  const uint32_t a_base =
      base + (warp_m * 64 + (lid & 15)) * G_RS + (lid >> 4) * 16;
  const int nrow = warp_n * 32 + (lid & 7) + ((lid >> 4) & 1) * 8;
  const uint32_t b_base = base + 2 * G_TILE + nrow * G_RS + ((lid >> 3) & 1) * 16;
#pragma unroll
  for (int kk = 0; kk < 4; kk++) {
    const int kb = kk * 32;
    uint32_t ah[4][4], al[4][4], bh[2][4], bl[2][4];
#pragma unroll
    for (int i = 0; i < 4; i++) {
      ldsm_x4(ah[i], a_base + i * (16 * G_RS) + kb);
      ldsm_x4(al[i], a_base + G_TILE + i * (16 * G_RS) + kb);
    }
#pragma unroll
    for (int jj = 0; jj < 2; jj++) {
      ldsm_x4(bh[jj], b_base + jj * (16 * G_RS) + kb);
      ldsm_x4(bl[jj], b_base + G_TILE + jj * (16 * G_RS) + kb);
    }
#pragma unroll
    for (int i = 0; i < 4; i++) {
#pragma unroll
      for (int j = 0; j < 4; j++) {
        const int jj = j >> 1, o = (j & 1) * 2;
        mma_bf16(acc[i][j], ah[i], bh[jj][o], bh[jj][o + 1]);
        mma_bf16(acc[i][j], ah[i], bl[jj][o], bl[jj][o + 1]);
        mma_bf16(acc[i][j], al[i], bh[jj][o], bh[jj][o + 1]);
      }
    }
  }
}

template <int K>
__global__ void __launch_bounds__(256, 1) gemm_mma(
    const __nv_bfloat16* __restrict__ Ah, const __nv_bfloat16* __restrict__ Al,
    const __nv_bfloat16* __restrict__ Bh, const __nv_bfloat16* __restrict__ Bl,
    const float* __restrict__ bias, float* __restrict__ C) {
  extern __shared__ char smem[];
  const uint32_t sb = smem_to_u32(smem);
  const int tid = threadIdx.x;
  const int wid = tid >> 5, lid = tid & 31;
  const int warp_m = wid & 1, warp_n = wid >> 1;
  const int bm = blockIdx.y * 128, bn = blockIdx.x * 128;
  const int NS = K / 64;

  float acc[4][4][4];
#pragma unroll
  for (int i = 0; i < 4; i++)
#pragma unroll
    for (int j = 0; j < 4; j++)
#pragma unroll
      for (int r = 0; r < 4; r++) acc[i][j][r] = 0.0f;

  stage_load<K>(Ah, Al, Bh, Bl, bm, bn, 0, sb, tid);
  CP_COMMIT();
  stage_load<K>(Ah, Al, Bh, Bl, bm, bn, 64, sb + G_STAGE, tid);
  CP_COMMIT();

  for (int s = 0; s < NS; s++) {
    CP_WAIT(1);
    __syncthreads();
    stage_compute(sb + (s & 1) * G_STAGE, warp_m, warp_n, lid, acc);
    __syncthreads();
    if (s + 2 < NS) {
      stage_load<K>(Ah, Al, Bh, Bl, bm, bn, (s + 2) * 64,
                    sb + ((s + 2) & 1) * G_STAGE, tid);
      CP_COMMIT();
    }
  }

  // epilogue: + bias, store fp32
  const int g = lid >> 2, tq = lid & 3;
#pragma unroll
  for (int j = 0; j < 4; j++) {
    const int n = bn + warp_n * 32 + j * 8 + tq * 2;
    const float2 bv = *reinterpret_cast<const float2*>(bias + n);
#pragma unroll
    for (int i = 0; i < 4; i++) {
      const int m = bm + warp_m * 64 + i * 16 + g;
      float2 r0 = {acc[i][j][0] + bv.x, acc[i][j][1] + bv.y};
      float2 r1 = {acc[i][j][2] + bv.x, acc[i][j][3] + bv.y};
      *reinterpret_cast<float2*>(C + (size_t)m * 512 + n) = r0;
      *reinterpret_cast<float2*>(C + (size_t)(m + 8) * 512 + n) = r1;
    }
  }
}

// ---------------------------------------------------------------------------
// BN stats (deterministic two-stage), BN+ReLU, 3-NN interp
// ---------------------------------------------------------------------------
__global__ void __launch_bounds__(512) colreduce(const float* __restrict__ X,
                                                 int M, float* __restrict__ part) {
  int c = threadIdx.x;
  float s = 0.0f, sq = 0.0f;
  for (int r = blockIdx.x; r < M; r += 128) {
    float v = X[(size_t)r * 512 + c];
    s += v;
    sq += v * v;
  }
  part[blockIdx.x * 512 + c] = s;
  part[65536 + blockIdx.x * 512 + c] = sq;
}

__global__ void __launch_bounds__(512) stats_finalize(
    const float* __restrict__ part, float invM,
    const float* __restrict__ gamma, const float* __restrict__ beta,
    float* __restrict__ ss) {
  int c = threadIdx.x;
  float s = 0.0f, sq = 0.0f;
  for (int b = 0; b < 128; b++) {
    s += part[b * 512 + c];
    sq += part[65536 + b * 512 + c];
  }
  float mu = s * invM;
  float var = sq * invM - mu * mu;
  float sc = gamma[c] * rsqrtf(var + 1e-5f);
  ss[c] = sc;
  ss[512 + c] = beta[c] - mu * sc;
}

__global__ void __launch_bounds__(256) bn_relu(float* __restrict__ X,
                                               size_t nVec4,
                                               const float* __restrict__ ss) {
  __shared__ float sc[512], sh[512];
  for (int c = threadIdx.x; c < 512; c += blockDim.x) {
    sc[c] = ss[c];
    sh[c] = ss[512 + c];
  }
  __syncthreads();
  float4* X4 = reinterpret_cast<float4*>(X);
  for (size_t i = blockIdx.x * (size_t)blockDim.x + threadIdx.x; i < nVec4;
       i += (size_t)gridDim.x * blockDim.x) {
    float4 v = X4[i];
    int c = (int)((i * 4) & 511);
    v.x = fmaxf(fmaf(v.x, sc[c + 0], sh[c + 0]), 0.0f);
    v.y = fmaxf(fmaf(v.y, sc[c + 1], sh[c + 1]), 0.0f);
    v.z = fmaxf(fmaf(v.z, sc[c + 2], sh[c + 2]), 0.0f);
    v.w = fmaxf(fmaf(v.w, sc[c + 3], sh[c + 3]), 0.0f);
    X4[i] = v;
  }
}

__global__ void __launch_bounds__(128) interp_add(
    const float* __restrict__ xyz2, const float* __restrict__ xyz1,
    const float* __restrict__ feats1, const float* __restrict__ feats2,
    float* __restrict__ outF) {
  __shared__ float sd[1024];
  __shared__ float rv[128];
  __shared__ int ri[128];
  __shared__ float b3v[3];
  __shared__ int b3i[3];

  const int tid = threadIdx.x;
  const int b = blockIdx.x >> 12;
  const int n = blockIdx.x & 4095;

  const float* pd = xyz2 + ((size_t)(b * 4096 + n)) * 3;
  const float px = pd[0], py = pd[1], pz = pd[2];
  const float pp = px * px + py * py + pz * pz;
  const float* src = xyz1 + (size_t)b * 1024 * 3;

  for (int s = tid; s < 1024; s += 128) {
    float sx = src[3 * s + 0];
    float sy = src[3 * s + 1];
    float sz = src[3 * s + 2];
    float ssn = sx * sx + sy * sy + sz * sz;
    float dt = px * sx + py * sy + pz * sz;
    sd[s] = pp + ssn - 2.0f * dt;
  }
  __syncthreads();

#pragma unroll
  for (int round = 0; round < 3; round++) {
    float lv = 1e30f;
    int li = 0x7fffffff;
#pragma unroll
    for (int j = 0; j < 8; j++) {
      int s = tid + j * 128;
      float v = sd[s];
      if (v < lv || (v == lv && s < li)) {
        lv = v;
        li = s;
      }
    }
    rv[tid] = lv;
    ri[tid] = li;
    __syncthreads();
    for (int off = 64; off > 0; off >>= 1) {
      if (tid < off) {
        float v2 = rv[tid + off];
        int i2 = ri[tid + off];
        if (v2 < rv[tid] || (v2 == rv[tid] && i2 < ri[tid])) {
          rv[tid] = v2;
          ri[tid] = i2;
        }
      }
      __syncthreads();
    }
    if (tid == 0) {
      b3v[round] = rv[0];
      b3i[round] = ri[0];
      sd[ri[0]] = 1e30f;
    }
    __syncthreads();
  }

  float w0 = 1.0f / (b3v[0] + 1e-8f);
  float w1 = 1.0f / (b3v[1] + 1e-8f);
  float w2 = 1.0f / (b3v[2] + 1e-8f);
  float inv = 1.0f / (w0 + w1 + w2);
  w0 *= inv;
  w1 *= inv;
  w2 *= inv;

  const float4* f0 =
      reinterpret_cast<const float4*>(feats1 + ((size_t)b * 1024 + b3i[0]) * 512);
  const float4* f1 =
      reinterpret_cast<const float4*>(feats1 + ((size_t)b * 1024 + b3i[1]) * 512);
  const float4* f2 =
      reinterpret_cast<const float4*>(feats1 + ((size_t)b * 1024 + b3i[2]) * 512);
  const float4* g =
      reinterpret_cast<const float4*>(feats2 + ((size_t)(b * 4096 + n)) * 512);
  float4* o = reinterpret_cast<float4*>(outF + ((size_t)(b * 4096 + n)) * 512);

  float4 a0 = f0[tid], a1 = f1[tid], a2 = f2[tid], gg = g[tid];
  float4 r;
  r.x = w0 * a0.x + w1 * a1.x + w2 * a2.x + gg.x;
  r.y = w0 * a0.y + w1 * a1.y + w2 * a2.y + gg.y;
  r.z = w0 * a0.z + w1 * a1.z + w2 * a2.z + gg.z;
  r.w = w0 * a0.w + w1 * a1.w + w2 * a2.w + gg.w;
  o[tid] = r;
}

// ---------------------------------------------------------------------------
extern "C" void kernel_launch(void* const* d_in, const int* in_sizes, int n_in,
                              void* d_out, int out_size) {
  const float* xyz1 = (const float*)d_in[0];
  const float* points1 = (const float*)d_in[1];
  const float* xyz2 = (const float*)d_in[2];
  const float* points2 = (const float*)d_in[3];
  const float* fc1_w = (const float*)d_in[4];
  const float* fc1_b = (const float*)d_in[5];
  const float* bn1_g = (const float*)d_in[6];
  const float* bn1_b = (const float*)d_in[7];
  const float* fc2_w = (const float*)d_in[8];
  const float* fc2_b = (const float*)d_in[9];
  const float* bn2_g = (const float*)d_in[10];
  const float* bn2_b = (const float*)d_in[11];
  float* out = (float*)d_out;

  float *h1, *h2, *part, *ss;
  __nv_bfloat16 *a1h, *a1l, *a2h, *a2l, *w1h, *w1l, *w2h, *w2l;
  cudaGetSymbolAddress((void**)&h1, g_h1);
  cudaGetSymbolAddress((void**)&h2, g_h2);
  cudaGetSymbolAddress((void**)&part, g_part);
  cudaGetSymbolAddress((void**)&ss, g_ss);
  cudaGetSymbolAddress((void**)&a1h, g_a1h);
  cudaGetSymbolAddress((void**)&a1l, g_a1l);
  cudaGetSymbolAddress((void**)&a2h, g_a2h);
  cudaGetSymbolAddress((void**)&a2l, g_a2l);
  cudaGetSymbolAddress((void**)&w1h, g_w1h);
  cudaGetSymbolAddress((void**)&w1l, g_w1l);
  cudaGetSymbolAddress((void**)&w2h, g_w2h);
  cudaGetSymbolAddress((void**)&w2l, g_w2l);

  cudaFuncSetAttribute(gemm_mma<1024>,
                       cudaFuncAttributeMaxDynamicSharedMemorySize, GEMM_SMEM);
  cudaFuncSetAttribute(gemm_mma<512>,
                       cudaFuncAttributeMaxDynamicSharedMemorySize, GEMM_SMEM);

  const size_t featElems = (size_t)16 * 4096 * 512;
  const size_t totalOut = (size_t)out_size;
  const size_t xyzElems = totalOut > featElems ? totalOut - featElems : 0;

  // bf16 hi/lo splits
  fsplit<<<4096, 256>>>(points1, a1h, a1l, (size_t)16384 * 1024 / 4);
  fsplit<<<4096, 256>>>(points2, a2h, a2l, (size_t)65536 * 512 / 4);
  wsplit<<<dim3(32, 16), 256>>>(fc1_w, w1h, w1l, 1024);
  wsplit<<<dim3(16, 16), 256>>>(fc2_w, w2h, w2l, 512);

  // Path 1: fc1 -> BN1 -> ReLU
  gemm_mma<1024><<<dim3(4, 128), 256, GEMM_SMEM>>>(a1h, a1l, w1h, w1l, fc1_b,
                                                   h1);
  colreduce<<<128, 512>>>(h1, 16384, part);
  stats_finalize<<<1, 512>>>(part, 1.0f / 16384.0f, bn1_g, bn1_b, ss);
  bn_relu<<<1024, 256>>>(h1, (size_t)16384 * 512 / 4, ss);

  // Path 2: fc2 -> BN2 -> ReLU
  gemm_mma<512><<<dim3(4, 512), 256, GEMM_SMEM>>>(a2h, a2l, w2h, w2l, fc2_b,
                                                  h2);
  colreduce<<<128, 512>>>(h2, 65536, part);
  stats_finalize<<<1, 512>>>(part, 1.0f / 65536.0f, bn2_g, bn2_b, ss + 1024);
  bn_relu<<<4096, 256>>>(h2, (size_t)65536 * 512 / 4, ss + 1024);

  // Output: [xyz2 passthrough | interp(feats1) + feats2]
  if (xyzElems > 0) {
    cudaMemcpyAsync(out, xyz2, xyzElems * sizeof(float),
                    cudaMemcpyDeviceToDevice);
  }
  interp_add<<<65536, 128>>>(xyz2, xyz1, h1, h2, out + xyzElems);
}